// round 1
// baseline (speedup 1.0000x reference)
#include <cuda_runtime.h>
#include <cuda_bf16.h>
#include <cstdint>

#define NN 100000
#define RR 8
#define EE 800000
#define DD 128
#define BB 4
#define RN (RR*NN)        // 800000
#define RE (RR*EE)        // 6400000
#define SCAN_BLOCKS ((RN + 1023) / 1024)   // 782

// ---------------- device scratch (static, no allocation) ----------------
__device__ int   g_is64;
__device__ int   g_deg[RN];
__device__ int   g_scan[RN];
__device__ int   g_bsum[1024];
__device__ int   g_bsumx[1024];
__device__ int   g_rowstart[RN];
__device__ int   g_cursor[RN];
__device__ float g_invdeg[RN];
__device__ int   g_csr[RE];
__device__ float g_Y[(size_t)NN * 512];   // 204.8 MB
__device__ float g_h1[(size_t)NN * DD];
__device__ float g_h2[(size_t)NN * DD];

// ---------------- edge index helpers ----------------
__device__ __forceinline__ int edge_at(const void* p, int i, int is64) {
    if (is64) return (int)((const long long*)p)[i];
    return ((const int*)p)[i];
}

// detect whether edge arrays are int64 or int32
__global__ void k_detect(const void* srcp, const void* dstp) {
    if (threadIdx.x == 0 && blockIdx.x == 0) {
        const long long* s = (const long long*)srcp;
        const long long* d = (const long long*)dstp;
        int ok = 1;
        for (int i = 0; i < 64; i++) {
            long long a = s[i], b = d[i];
            if (a < 0 || a >= NN || b < 0 || b >= NN) { ok = 0; break; }
        }
        g_is64 = ok;
    }
}

__global__ void k_zero() {
    int i = blockIdx.x * blockDim.x + threadIdx.x;
    if (i < RN) { g_deg[i] = 0; g_cursor[i] = 0; }
}

__global__ void k_degree(const void* dstp) {
    int i = blockIdx.x * blockDim.x + threadIdx.x;
    if (i >= RE) return;
    int is64 = g_is64;
    int d = edge_at(dstp, i, is64);
    int r = i / EE;
    atomicAdd(&g_deg[r * NN + d], 1);
}

// block-level inclusive scan (Hillis-Steele) of g_deg -> g_scan, block sums -> g_bsum
__global__ void k_scan1() {
    __shared__ int sh[1024];
    int gid = blockIdx.x * 1024 + threadIdx.x;
    int v = (gid < RN) ? g_deg[gid] : 0;
    sh[threadIdx.x] = v;
    __syncthreads();
    for (int off = 1; off < 1024; off <<= 1) {
        int t = (threadIdx.x >= off) ? sh[threadIdx.x - off] : 0;
        __syncthreads();
        sh[threadIdx.x] += t;
        __syncthreads();
    }
    if (gid < RN) g_scan[gid] = sh[threadIdx.x];
    if (threadIdx.x == 1023) g_bsum[blockIdx.x] = sh[1023];
}

// exclusive scan of block sums (single block)
__global__ void k_scan2(int nb) {
    __shared__ int sh[1024];
    int v = (threadIdx.x < nb) ? g_bsum[threadIdx.x] : 0;
    sh[threadIdx.x] = v;
    __syncthreads();
    for (int off = 1; off < 1024; off <<= 1) {
        int t = (threadIdx.x >= off) ? sh[threadIdx.x - off] : 0;
        __syncthreads();
        sh[threadIdx.x] += t;
        __syncthreads();
    }
    if (threadIdx.x < nb) g_bsumx[threadIdx.x] = sh[threadIdx.x] - v;
}

// final rowstart (exclusive scan) + invdeg
__global__ void k_scan3() {
    int gid = blockIdx.x * blockDim.x + threadIdx.x;
    if (gid >= RN) return;
    int deg = g_deg[gid];
    g_rowstart[gid] = g_scan[gid] - deg + g_bsumx[gid / 1024];
    g_invdeg[gid] = 1.0f / (float)max(deg, 1);
}

__global__ void k_fill(const void* srcp, const void* dstp) {
    int i = blockIdx.x * blockDim.x + threadIdx.x;
    if (i >= RE) return;
    int is64 = g_is64;
    int s = edge_at(srcp, i, is64);
    int d = edge_at(dstp, i, is64);
    int r = i / EE;
    int row = r * NN + d;
    int pos = g_rowstart[row] + atomicAdd(&g_cursor[row], 1);
    g_csr[pos] = s;
}

// One warp per destination node; accumulates all 8 relations, folds the basis
// combination w_comp[r][b] * invdeg on the fly, writes Y[n, 0:512].
__global__ void k_gather(const float* __restrict__ x, const float* __restrict__ wcomp) {
    __shared__ float swc[RR * BB];
    if (threadIdx.x < RR * BB) swc[threadIdx.x] = wcomp[threadIdx.x];
    __syncthreads();
    int warp = threadIdx.x >> 5;
    int lane = threadIdx.x & 31;
    int n = blockIdx.x * 8 + warp;
    if (n >= NN) return;

    float4 acc[BB];
    #pragma unroll
    for (int b = 0; b < BB; b++) acc[b] = make_float4(0.f, 0.f, 0.f, 0.f);

    #pragma unroll
    for (int r = 0; r < RR; r++) {
        int row = r * NN + n;
        int st = g_rowstart[row];
        int len = g_deg[row];
        float t0 = 0.f, t1 = 0.f, t2 = 0.f, t3 = 0.f;
        for (int j = 0; j < len; j++) {
            int s = g_csr[st + j];                       // uniform across warp (broadcast)
            float4 v = *(const float4*)&x[(size_t)s * DD + lane * 4];
            t0 += v.x; t1 += v.y; t2 += v.z; t3 += v.w;
        }
        float iv = g_invdeg[row];
        #pragma unroll
        for (int b = 0; b < BB; b++) {
            float c = swc[r * BB + b] * iv;
            acc[b].x += c * t0; acc[b].y += c * t1;
            acc[b].z += c * t2; acc[b].w += c * t3;
        }
    }
    #pragma unroll
    for (int b = 0; b < BB; b++)
        *(float4*)&g_Y[(size_t)n * 512 + b * DD + lane * 4] = acc[b];
}

// ---------------- SIMT fp32 GEMM: C[M,128] = A[M,K] @ B[K,128] ----------------
// 128x128 block tile, 8x8 microtile per thread (strided mapping: rows ty+16i, cols tx+16j)
__global__ void __launch_bounds__(256, 2)
k_gemm(const float* __restrict__ A, int K, int M,
       const float* __restrict__ Bm,
       const float* __restrict__ Cin,
       float* __restrict__ Cout,
       const float* __restrict__ bias,
       int relu) {
    __shared__ float As[16][132];   // transposed A tile, padded
    __shared__ float Bs[16][128];
    int t = threadIdx.x;
    int tx = t & 15, ty = t >> 4;
    int r0 = blockIdx.x * 128;

    float acc[8][8];
    #pragma unroll
    for (int i = 0; i < 8; i++)
        #pragma unroll
        for (int j = 0; j < 8; j++) acc[i][j] = 0.f;

    for (int kt = 0; kt < K; kt += 16) {
        // load A tile (rows r0..r0+127, cols kt..kt+15), transposed into As
        int rowA = t >> 2;
        int colA = (t & 3) * 4;
        #pragma unroll
        for (int p = 0; p < 2; p++) {
            int rr = rowA + p * 64;
            int gr = r0 + rr;
            float4 v = make_float4(0.f, 0.f, 0.f, 0.f);
            if (gr < M) v = *(const float4*)&A[(size_t)gr * K + kt + colA];
            As[colA + 0][rr] = v.x; As[colA + 1][rr] = v.y;
            As[colA + 2][rr] = v.z; As[colA + 3][rr] = v.w;
        }
        // load B tile (rows kt..kt+15, all 128 cols)
        int rowB = t >> 5;
        int colB = (t & 31) * 4;
        #pragma unroll
        for (int p = 0; p < 2; p++) {
            int rb = rowB + p * 8;
            float4 v = *(const float4*)&Bm[(size_t)(kt + rb) * 128 + colB];
            *(float4*)&Bs[rb][colB] = v;
        }
        __syncthreads();
        #pragma unroll
        for (int k = 0; k < 16; k++) {
            float a[8], b[8];
            #pragma unroll
            for (int i = 0; i < 8; i++) a[i] = As[k][ty + 16 * i];
            #pragma unroll
            for (int j = 0; j < 8; j++) b[j] = Bs[k][tx + 16 * j];
            #pragma unroll
            for (int i = 0; i < 8; i++)
                #pragma unroll
                for (int j = 0; j < 8; j++) acc[i][j] += a[i] * b[j];
        }
        __syncthreads();
    }
    // epilogue
    #pragma unroll
    for (int i = 0; i < 8; i++) {
        int gr = r0 + ty + 16 * i;
        if (gr >= M) continue;
        #pragma unroll
        for (int j = 0; j < 8; j++) {
            int gc = tx + 16 * j;
            float v = acc[i][j];
            if (Cin)  v += Cin[(size_t)gr * 128 + gc];
            if (bias) v += bias[gc];
            if (relu) v = fmaxf(v, 0.f);
            Cout[(size_t)gr * 128 + gc] = v;
        }
    }
}

// ---------------- launch ----------------
extern "C" void kernel_launch(void* const* d_in, const int* in_sizes, int n_in,
                              void* d_out, int out_size) {
    const float* x      = (const float*)d_in[0];
    const void*  esrc   = d_in[1];
    const void*  edst   = d_in[2];
    const float* wcomp  = (const float*)d_in[3];
    const float* bases  = (const float*)d_in[4];   // [4,128,128] == flat [512,128]
    const float* loopw  = (const float*)d_in[5];
    const float* hbias  = (const float*)d_in[6];
    const float* ngnn   = (const float*)d_in[7];   // [2,128,128]
    float* out = (float*)d_out;

    float *pY, *pH1, *pH2;
    cudaGetSymbolAddress((void**)&pY,  g_Y);
    cudaGetSymbolAddress((void**)&pH1, g_h1);
    cudaGetSymbolAddress((void**)&pH2, g_h2);

    k_detect<<<1, 32>>>(esrc, edst);
    k_zero<<<(RN + 255) / 256, 256>>>();
    k_degree<<<RE / 256, 256>>>(edst);
    k_scan1<<<SCAN_BLOCKS, 1024>>>();
    k_scan2<<<1, 1024>>>(SCAN_BLOCKS);
    k_scan3<<<(RN + 255) / 256, 256>>>();
    k_fill<<<RE / 256, 256>>>(esrc, edst);
    k_gather<<<(NN + 7) / 8, 256>>>(x, wcomp);

    int gblocks = (NN + 127) / 128;
    // h1 = Y @ bases_flat   (relation part, basis-fused, K=512)
    k_gemm<<<gblocks, 256>>>(pY, 512, NN, bases, nullptr, pH1, nullptr, 0);
    // h1 = relu(h1 + x @ loop_weight + bias)
    k_gemm<<<gblocks, 256>>>(x, 128, NN, loopw, pH1, pH1, hbias, 1);
    // h2 = relu(h1 @ ngnn_w[0])
    k_gemm<<<gblocks, 256>>>(pH1, 128, NN, ngnn, nullptr, pH2, nullptr, 1);
    // out = relu(h2 @ ngnn_w[1])
    k_gemm<<<gblocks, 256>>>(pH2, 128, NN, ngnn + 128 * 128, nullptr, out, nullptr, 1);
}